// round 1
// baseline (speedup 1.0000x reference)
#include <cuda_runtime.h>
#include <cstdint>
#include <cstddef>

// ---------------- problem constants ----------------
#define T_STEPS 16384
#define HDIM    512
#define GDIM    1536          // 3*H
// scan decomposition
#define NCTA    32
#define HPC     16            // HDIM / NCTA  (h elements per CTA)
#define RPC     48            // GDIM / NCTA  (W_hh rows per CTA: 3 gates x HPC)
#define NTH     384           // RPC * 8 threads (8 lanes per row)

// ---------------- device scratch ----------------
__device__ float    g_gi[(size_t)T_STEPS * GDIM];  // precomputed input gates (100 MB)
__device__ float    g_h[2][HDIM];                  // double-buffered hidden state
__device__ unsigned g_bar;                         // barrier counter

// ---------------- init: reset state each launch ----------------
__global__ void scan_init() {
    int t = threadIdx.x;
    if (t < HDIM) g_h[0][t] = 0.f;
    if (t == 0)   g_bar = 0u;
}

// ---------------- GEMM: gi = x @ W_ih^T + b_ih ----------------
#define BM 128
#define BN 128
#define BK 8

__global__ void __launch_bounds__(256) gemm_gi(
    const float* __restrict__ x, const float* __restrict__ Wih,
    const float* __restrict__ bih) {
    __shared__ __align__(16) float As[BK][BM];
    __shared__ __align__(16) float Bs[BK][BN];
    const int bn  = blockIdx.x;        // 0..11
    const int bm  = blockIdx.y;        // 0..127
    const int tid = threadIdx.x;
    const int tx  = tid & 15;
    const int ty  = tid >> 4;

    const int lrow = tid >> 1;
    const int lseg = (tid & 1) * 4;
    const float* xp = x   + (size_t)(bm * BM + lrow) * HDIM + lseg;
    const float* wp = Wih + (size_t)(bn * BN + lrow) * HDIM + lseg;

    float acc[8][8];
#pragma unroll
    for (int i = 0; i < 8; i++)
#pragma unroll
        for (int j = 0; j < 8; j++) acc[i][j] = 0.f;

    for (int k0 = 0; k0 < HDIM; k0 += BK) {
        float4 av = *(const float4*)(xp + k0);
        float4 bv = *(const float4*)(wp + k0);
        As[lseg + 0][lrow] = av.x; As[lseg + 1][lrow] = av.y;
        As[lseg + 2][lrow] = av.z; As[lseg + 3][lrow] = av.w;
        Bs[lseg + 0][lrow] = bv.x; Bs[lseg + 1][lrow] = bv.y;
        Bs[lseg + 2][lrow] = bv.z; Bs[lseg + 3][lrow] = bv.w;
        __syncthreads();
#pragma unroll
        for (int k = 0; k < BK; k++) {
            float4 a0 = *(const float4*)&As[k][ty * 8];
            float4 a1 = *(const float4*)&As[k][ty * 8 + 4];
            float4 b0 = *(const float4*)&Bs[k][tx * 8];
            float4 b1 = *(const float4*)&Bs[k][tx * 8 + 4];
            float a[8] = {a0.x, a0.y, a0.z, a0.w, a1.x, a1.y, a1.z, a1.w};
            float b[8] = {b0.x, b0.y, b0.z, b0.w, b1.x, b1.y, b1.z, b1.w};
#pragma unroll
            for (int i = 0; i < 8; i++)
#pragma unroll
                for (int j = 0; j < 8; j++)
                    acc[i][j] = fmaf(a[i], b[j], acc[i][j]);
        }
        __syncthreads();
    }
#pragma unroll
    for (int i = 0; i < 8; i++) {
        int row = bm * BM + ty * 8 + i;
        float* gp = &g_gi[(size_t)row * GDIM + bn * BN + tx * 8];
#pragma unroll
        for (int j = 0; j < 8; j++)
            gp[j] = acc[i][j] + bih[bn * BN + tx * 8 + j];
    }
}

// ---------------- scan helpers ----------------
__device__ __forceinline__ float f32x2_hsum(unsigned long long a) {
    float lo, hi;
    asm("mov.b64 {%0,%1}, %2;" : "=f"(lo), "=f"(hi) : "l"(a));
    return lo + hi;
}

#define SCAN_SMEM_FLOATS (RPC * HDIM + RPC + 2 * RPC + RPC)
#define SCAN_SMEM_BYTES  (SCAN_SMEM_FLOATS * 4)

// ---------------- persistent GRU scan ----------------
__global__ void __launch_bounds__(NTH, 1) gru_scan(
    const float* __restrict__ Whh, const float* __restrict__ bhh,
    float* __restrict__ out) {
    extern __shared__ float smem[];
    float* w_s   = smem;                 // RPC*HDIM  : W_hh slice (resident)
    float* red_s = w_s + RPC * HDIM;     // RPC       : per-row dot results
    float* gi_s  = red_s + RPC;          // 2*RPC     : double-buffered gi
    float* bhh_s = gi_s + 2 * RPC;       // RPC

    const int c   = blockIdx.x;
    const int tid = threadIdx.x;
    const int lr  = tid >> 3;            // local row 0..47
    const int j   = tid & 7;             // lane within row
    const int goff = j * 4;

    // load weight slice: local row r -> global row (r/HPC)*HDIM + c*HPC + (r%HPC)
    for (int idx = tid; idx < RPC * HDIM; idx += NTH) {
        int r = idx >> 9;
        int k = idx & (HDIM - 1);
        int gr = (r / HPC) * HDIM + c * HPC + (r % HPC);
        w_s[idx] = Whh[(size_t)gr * HDIM + k];
    }
    if (tid < RPC) {
        int gr = (tid / HPC) * HDIM + c * HPC + (tid % HPC);
        bhh_s[tid] = bhh[gr];
        gi_s[tid]  = g_gi[gr];           // gi for t=0 (parity 0 slot)
    }
    __syncthreads();

    const float* wrow = w_s + lr * HDIM;
    const int hbase = c * HPC;

    for (int t = 0; t < T_STEPS; ++t) {
        const int par = t & 1;

        // prefetch gi(t+1) into registers (latency hides under matvec)
        float gi_pf = 0.f;
        const bool pf = (tid < RPC) && (t + 1 < T_STEPS);
        if (pf) {
            int gr = (tid / HPC) * HDIM + c * HPC + (tid % HPC);
            gi_pf = __ldg(&g_gi[(size_t)(t + 1) * GDIM + gr]);
        }

        // matvec: h read directly from global (fresh after acquire fence)
        const float* hsrc = g_h[par];
        unsigned long long a0 = 0ull, a1 = 0ull;
#pragma unroll
        for (int s = 0; s < 16; ++s) {
            ulonglong2 wv = *(const ulonglong2*)(wrow + goff + s * 32);
            ulonglong2 hv = *(const ulonglong2*)(hsrc + goff + s * 32);
            asm("fma.rn.f32x2 %0, %1, %2, %0;" : "+l"(a0) : "l"(wv.x), "l"(hv.x));
            asm("fma.rn.f32x2 %0, %1, %2, %0;" : "+l"(a1) : "l"(wv.y), "l"(hv.y));
        }
        float acc = f32x2_hsum(a0) + f32x2_hsum(a1);
        acc += __shfl_xor_sync(0xffffffffu, acc, 4);
        acc += __shfl_xor_sync(0xffffffffu, acc, 2);
        acc += __shfl_xor_sync(0xffffffffu, acc, 1);
        if (j == 0) red_s[lr] = acc;
        if (pf) gi_s[(par ^ 1) * RPC + tid] = gi_pf;
        __syncthreads();

        // gate math on HPC threads
        if (tid < HPC) {
            const int i = tid;
            float ghr = red_s[i]           + bhh_s[i];
            float ghz = red_s[HPC + i]     + bhh_s[HPC + i];
            float ghn = red_s[2 * HPC + i] + bhh_s[2 * HPC + i];
            float gir = gi_s[par * RPC + i];
            float giz = gi_s[par * RPC + HPC + i];
            float gin = gi_s[par * RPC + 2 * HPC + i];
            float r = 1.f / (1.f + __expf(-(gir + ghr)));
            float z = 1.f / (1.f + __expf(-(giz + ghz)));
            float n = tanhf(gin + r * ghn);
            float hold = hsrc[hbase + i];
            float hnew = (1.f - z) * n + z * hold;
            out[(size_t)t * HDIM + hbase + i] = hnew;
            g_h[par ^ 1][hbase + i] = hnew;
            __threadfence();             // release: h visible gpu-wide (+L1 inval)
        }
        __syncthreads();

        if (t + 1 < T_STEPS) {
            if (tid == 0) {
                atomicAdd(&g_bar, 1u);
                const unsigned target = (unsigned)(t + 1) * NCTA;
                while (*((volatile unsigned*)&g_bar) < target) { }
                __threadfence();         // acquire: invalidate L1 before h reads
            }
            __syncthreads();
        }
    }
}

// ---------------- launch ----------------
extern "C" void kernel_launch(void* const* d_in, const int* in_sizes, int n_in,
                              void* d_out, int out_size) {
    const float* x   = (const float*)d_in[0];
    const float* Wih = (const float*)d_in[1];
    const float* Whh = (const float*)d_in[2];
    const float* bih = (const float*)d_in[3];
    const float* bhh = (const float*)d_in[4];
    float* out = (float*)d_out;

    cudaFuncSetAttribute(gru_scan, cudaFuncAttributeMaxDynamicSharedMemorySize,
                         SCAN_SMEM_BYTES);

    scan_init<<<1, 512>>>();
    dim3 ggrid(GDIM / BN, T_STEPS / BM);   // (12, 128)
    gemm_gi<<<ggrid, 256>>>(x, Wih, bih);
    gru_scan<<<NCTA, NTH, SCAN_SMEM_BYTES>>>(Whh, bhh, out);
}